// round 10
// baseline (speedup 1.0000x reference)
#include <cuda_runtime.h>
#include <cuda_bf16.h>
#include <cstdint>

// Problem constants (shapes fixed by the dataset; sizes re-derived from in_sizes)
#define MAX_NODES 100000
#define MAX_EDGES 1600000
#define IN_DIM    64
#define HID_DIM   32
#define SCAN_TILE 1024            // elems per block in scan phase (256 thr x 4)
#define MAX_PARTIALS 128          // supports n <= 131072

// Scratch (allocation-free rule: __device__ globals)
__device__ int   g_deg_out[MAX_NODES];
__device__ int   g_deg_in [MAX_NODES];
__device__ int   g_row_ptr[MAX_NODES + 1];
__device__ int   g_cursor [MAX_NODES];
__device__ int   g_partial[MAX_PARTIALS];
__device__ int   g_csr_src[MAX_EDGES];
__device__ float g_h      [MAX_NODES * HID_DIM];   // (X@W) * norm_src

// ---------------------------------------------------------------------------
// K0: zero both degree arrays with int4 stores
// ---------------------------------------------------------------------------
__global__ void k_zero_deg(int n) {
    int n4 = n >> 2;
    int i = blockIdx.x * blockDim.x + threadIdx.x;
    int4 z = make_int4(0, 0, 0, 0);
    if (i < n4) {
        reinterpret_cast<int4*>(g_deg_out)[i] = z;
        reinterpret_cast<int4*>(g_deg_in )[i] = z;
    }
    // tail
    int t = n4 * 4 + i;
    if (i < (n & 3)) { g_deg_out[t] = 0; g_deg_in[t] = 0; }
}

// ---------------------------------------------------------------------------
// K1: fused degree histograms (in + out), 4 edges/thread via int4 loads.
//     8 independent REDGs per thread -> latency hidden, throughput bound.
// ---------------------------------------------------------------------------
__global__ void k_hist(const int* __restrict__ src, const int* __restrict__ dst, int E) {
    int base = (blockIdx.x * blockDim.x + threadIdx.x) * 4;
    if (base + 3 < E) {
        int4 s = __ldg(reinterpret_cast<const int4*>(src + base));
        int4 d = __ldg(reinterpret_cast<const int4*>(dst + base));
        atomicAdd(&g_deg_out[s.x], 1); atomicAdd(&g_deg_in[d.x], 1);
        atomicAdd(&g_deg_out[s.y], 1); atomicAdd(&g_deg_in[d.y], 1);
        atomicAdd(&g_deg_out[s.z], 1); atomicAdd(&g_deg_in[d.z], 1);
        atomicAdd(&g_deg_out[s.w], 1); atomicAdd(&g_deg_in[d.w], 1);
    } else {
        for (int i = base; i < E; i++) {
            atomicAdd(&g_deg_out[__ldg(src + i)], 1);
            atomicAdd(&g_deg_in [__ldg(dst + i)], 1);
        }
    }
}

// ---------------------------------------------------------------------------
// K2a: per-block local exclusive scan. Each thread: 4 coalesced elems (int4).
//      Writes block-local exclusive prefixes into g_row_ptr and the block
//      total into g_partial[blockIdx].
// ---------------------------------------------------------------------------
__global__ void k_scan_local(int n) {
    __shared__ int sw[256];
    int t = threadIdx.x;
    int idx = blockIdx.x * SCAN_TILE + t * 4;

    int v0 = 0, v1 = 0, v2 = 0, v3 = 0;
    if (idx + 3 < n) {
        int4 v = *reinterpret_cast<const int4*>(g_deg_in + idx);
        v0 = v.x; v1 = v.y; v2 = v.z; v3 = v.w;
    } else {
        if (idx + 0 < n) v0 = g_deg_in[idx + 0];
        if (idx + 1 < n) v1 = g_deg_in[idx + 1];
        if (idx + 2 < n) v2 = g_deg_in[idx + 2];
    }

    sw[t] = v0 + v1 + v2 + v3;
    __syncthreads();
    for (int off = 1; off < 256; off <<= 1) {
        int u = (t >= off) ? sw[t - off] : 0;
        __syncthreads();
        sw[t] += u;
        __syncthreads();
    }
    int excl = (t == 0) ? 0 : sw[t - 1];

    if (idx + 0 < n) g_row_ptr[idx + 0] = excl;
    if (idx + 1 < n) g_row_ptr[idx + 1] = excl + v0;
    if (idx + 2 < n) g_row_ptr[idx + 2] = excl + v0 + v1;
    if (idx + 3 < n) g_row_ptr[idx + 3] = excl + v0 + v1 + v2;
    if (t == 255) g_partial[blockIdx.x] = sw[255];
}

// ---------------------------------------------------------------------------
// K2b: add block offsets (each block redundantly warp-reduces the partials
//      preceding its tile — 98 ints, free), write cursor copy, cap row_ptr[n].
// ---------------------------------------------------------------------------
__global__ void k_scan_addoff(int n, int E) {
    __shared__ int s_off;
    if (threadIdx.x < 32) {
        int sum = 0;
        for (int j = threadIdx.x; j < blockIdx.x; j += 32)
            sum += g_partial[j];
#pragma unroll
        for (int off = 16; off > 0; off >>= 1)
            sum += __shfl_down_sync(0xffffffffu, sum, off);
        if (threadIdx.x == 0) s_off = sum;
    }
    __syncthreads();
    int off = s_off;

    int idx = blockIdx.x * SCAN_TILE + threadIdx.x * 4;
    if (idx + 3 < n) {
        int4 v = *reinterpret_cast<const int4*>(g_row_ptr + idx);
        v.x += off; v.y += off; v.z += off; v.w += off;
        *reinterpret_cast<int4*>(g_row_ptr + idx) = v;
        *reinterpret_cast<int4*>(g_cursor  + idx) = v;
    } else {
        for (int i = idx; i < n; i++) {
            int v = g_row_ptr[i] + off;
            g_row_ptr[i] = v;
            g_cursor[i]  = v;
        }
    }
    if (blockIdx.x == 0 && threadIdx.x == 0) g_row_ptr[n] = E;
}

// ---------------------------------------------------------------------------
// K3: CSR fill (counting-sort placement). 8 edges/thread -> 8 independent
//     ATOMG cursors in flight (latency 318cyc hidden by MLP).
// ---------------------------------------------------------------------------
__global__ void k_fill(const int* __restrict__ src, const int* __restrict__ dst, int E) {
    int base = (blockIdx.x * blockDim.x + threadIdx.x) * 8;
    if (base + 7 < E) {
        int4 s0 = __ldg(reinterpret_cast<const int4*>(src + base));
        int4 s1 = __ldg(reinterpret_cast<const int4*>(src + base + 4));
        int4 d0 = __ldg(reinterpret_cast<const int4*>(dst + base));
        int4 d1 = __ldg(reinterpret_cast<const int4*>(dst + base + 4));
        int p0 = atomicAdd(&g_cursor[d0.x], 1);
        int p1 = atomicAdd(&g_cursor[d0.y], 1);
        int p2 = atomicAdd(&g_cursor[d0.z], 1);
        int p3 = atomicAdd(&g_cursor[d0.w], 1);
        int p4 = atomicAdd(&g_cursor[d1.x], 1);
        int p5 = atomicAdd(&g_cursor[d1.y], 1);
        int p6 = atomicAdd(&g_cursor[d1.z], 1);
        int p7 = atomicAdd(&g_cursor[d1.w], 1);
        g_csr_src[p0] = s0.x;
        g_csr_src[p1] = s0.y;
        g_csr_src[p2] = s0.z;
        g_csr_src[p3] = s0.w;
        g_csr_src[p4] = s1.x;
        g_csr_src[p5] = s1.y;
        g_csr_src[p6] = s1.z;
        g_csr_src[p7] = s1.w;
    } else {
        for (int i = base; i < E; i++) {
            int s = __ldg(src + i);
            int d = __ldg(dst + i);
            int p = atomicAdd(&g_cursor[d], 1);
            g_csr_src[p] = s;
        }
    }
}

// ---------------------------------------------------------------------------
// K4: h = (X @ W) * rsqrt(max(deg_out,1))
// ---------------------------------------------------------------------------
__global__ void k_gemm_norm(const float* __restrict__ X,
                            const float* __restrict__ W,
                            int n) {
    __shared__ float sW[IN_DIM * HID_DIM];   // 8 KB
    for (int i = threadIdx.x; i < IN_DIM * HID_DIM; i += blockDim.x)
        sW[i] = W[i];
    __syncthreads();

    int r = blockIdx.x * blockDim.x + threadIdx.x;
    if (r >= n) return;

    float acc[HID_DIM];
#pragma unroll
    for (int j = 0; j < HID_DIM; j++) acc[j] = 0.f;

    const float4* xr = reinterpret_cast<const float4*>(X + (size_t)r * IN_DIM);
#pragma unroll 4
    for (int k4 = 0; k4 < IN_DIM / 4; k4++) {
        float4 x = __ldg(xr + k4);
        int k = k4 * 4;
#pragma unroll
        for (int j = 0; j < HID_DIM; j++) {
            acc[j] = fmaf(x.x, sW[(k + 0) * HID_DIM + j],
                     fmaf(x.y, sW[(k + 1) * HID_DIM + j],
                     fmaf(x.z, sW[(k + 2) * HID_DIM + j],
                     fmaf(x.w, sW[(k + 3) * HID_DIM + j], acc[j]))));
        }
    }

    float nrm = rsqrtf(fmaxf((float)g_deg_out[r], 1.0f));
    float4* hr = reinterpret_cast<float4*>(g_h + (size_t)r * HID_DIM);
#pragma unroll
    for (int j4 = 0; j4 < HID_DIM / 4; j4++) {
        float4 v;
        v.x = acc[j4 * 4 + 0] * nrm;
        v.y = acc[j4 * 4 + 1] * nrm;
        v.z = acc[j4 * 4 + 2] * nrm;
        v.w = acc[j4 * 4 + 3] * nrm;
        hr[j4] = v;
    }
}

// ---------------------------------------------------------------------------
// K5: pull-style aggregation + finalize. One warp per dst node.
//     g = lane>>3 (edge sub-slot), p = lane&7 (float4 slice).
//     Edge loop unrolled x2: 8 edges in flight per warp, the two dependent
//     index->gather chains overlap. Shfl reduce, fused norm+bias+relu.
// ---------------------------------------------------------------------------
__global__ void k_aggregate(float* __restrict__ out,
                            const float* __restrict__ b,
                            int n) {
    int warp = (blockIdx.x * blockDim.x + threadIdx.x) >> 5;
    if (warp >= n) return;
    int lane = threadIdx.x & 31;
    int p = lane & 7;
    int g = lane >> 3;

    int start = __ldg(&g_row_ptr[warp]);
    int end   = __ldg(&g_row_ptr[warp + 1]);

    const float4* h4 = reinterpret_cast<const float4*>(g_h);
    float4 acc = make_float4(0.f, 0.f, 0.f, 0.f);

    int j = start + g;
    // unroll x2: both index loads issue before either gather is consumed
    for (; j + 4 < end; j += 8) {
        int s0 = __ldg(&g_csr_src[j]);
        int s1 = __ldg(&g_csr_src[j + 4]);
        float4 v0 = __ldg(h4 + (size_t)s0 * (HID_DIM / 4) + p);
        float4 v1 = __ldg(h4 + (size_t)s1 * (HID_DIM / 4) + p);
        acc.x += v0.x + v1.x;
        acc.y += v0.y + v1.y;
        acc.z += v0.z + v1.z;
        acc.w += v0.w + v1.w;
    }
    if (j < end) {
        int s = __ldg(&g_csr_src[j]);
        float4 v = __ldg(h4 + (size_t)s * (HID_DIM / 4) + p);
        acc.x += v.x; acc.y += v.y; acc.z += v.z; acc.w += v.w;
    }

#pragma unroll
    for (int off = 16; off >= 8; off >>= 1) {
        acc.x += __shfl_down_sync(0xffffffffu, acc.x, off);
        acc.y += __shfl_down_sync(0xffffffffu, acc.y, off);
        acc.z += __shfl_down_sync(0xffffffffu, acc.z, off);
        acc.w += __shfl_down_sync(0xffffffffu, acc.w, off);
    }

    if (g == 0) {
        float nrm = rsqrtf(fmaxf((float)(end - start), 1.0f));
        float4 bb = __ldg(reinterpret_cast<const float4*>(b) + p);
        float4 v;
        v.x = fmaxf(acc.x * nrm + bb.x, 0.f);
        v.y = fmaxf(acc.y * nrm + bb.y, 0.f);
        v.z = fmaxf(acc.z * nrm + bb.z, 0.f);
        v.w = fmaxf(acc.w * nrm + bb.w, 0.f);
        reinterpret_cast<float4*>(out)[(size_t)warp * (HID_DIM / 4) + p] = v;
    }
}

// ---------------------------------------------------------------------------
extern "C" void kernel_launch(void* const* d_in, const int* in_sizes, int n_in,
                              void* d_out, int out_size) {
    const float* features = (const float*)d_in[0];
    const int*   src      = (const int*)  d_in[1];
    const int*   dst      = (const int*)  d_in[2];
    const float* W        = (const float*)d_in[3];
    const float* b        = (const float*)d_in[4];
    float*       out      = (float*)d_out;

    int n = in_sizes[0] / IN_DIM;   // 100000
    int E = in_sizes[1];            // 1600000

    const int B = 256;
    int nb = (n + SCAN_TILE - 1) / SCAN_TILE;   // 98 scan tiles

    // K0: zero degree counters (int4)
    int z4 = (n >> 2) + 4;
    k_zero_deg<<<(z4 + B - 1) / B, B>>>(n);

    // K1: fused in/out degree histograms (4 edges/thread)
    int histThreads = (E + 3) / 4;
    k_hist<<<(histThreads + B - 1) / B, B>>>(src, dst, E);

    // K2: two-phase exclusive scan -> row_ptr, cursor
    k_scan_local<<<nb, 256>>>(n);
    k_scan_addoff<<<nb, 256>>>(n, E);

    // K3: CSR fill (8 edges/thread, MLP=8 on cursor atomics)
    int fillThreads = (E + 7) / 8;
    k_fill<<<(fillThreads + B - 1) / B, B>>>(src, dst, E);

    // K4: gemm + src-norm
    k_gemm_norm<<<(n + B - 1) / B, B>>>(features, W, n);

    // K5: pull aggregation + norm_dst + bias + relu (one warp per node)
    long long threads5 = (long long)n * 32;
    k_aggregate<<<(int)((threads5 + B - 1) / B), B>>>(out, b, n);
}